// round 2
// baseline (speedup 1.0000x reference)
#include <cuda_runtime.h>
#include <math.h>

#define BB 4
#define CC 64
#define WW 128
#define HH 128
#define KK 9
#define OCC 64
#define GG 16
#define EPSV 1e-5f

// Scratch (static device globals — no allocation allowed)
__device__ __align__(16) float g_fT[BB * WW * HH * CC];   // NHWC: ((b*W+y)*H+x)*C + c
__device__ __align__(16) float g_y[BB * KK * WW * HH];    // y coords
__device__ float g_stats[BB * GG * 2];                    // (sum, sumsq) per (b, group)

// ---------------------------------------------------------------------------
// Kernel 0: NCHW -> NHWC transpose of f
// grid (B*W, H/32, C/32), block (32, 8)
// ---------------------------------------------------------------------------
__global__ void transpose_kernel(const float* __restrict__ f) {
    __shared__ float tile[32][33];
    const int by = blockIdx.x;          // b*128 + y
    const int b = by >> 7, y = by & 127;
    const int x0 = blockIdx.y * 32;
    const int c0 = blockIdx.z * 32;
    #pragma unroll
    for (int i = threadIdx.y; i < 32; i += 8) {
        tile[i][threadIdx.x] = f[((b * CC + c0 + i) * WW + y) * HH + x0 + threadIdx.x];
    }
    __syncthreads();
    #pragma unroll
    for (int i = threadIdx.y; i < 32; i += 8) {
        g_fT[((b * WW + y) * HH + x0 + i) * CC + c0 + threadIdx.x] = tile[threadIdx.x][i];
    }
}

// ---------------------------------------------------------------------------
// Kernel A: offset conv (only 9 of 18 out channels needed) + BN + tanh +
// partial cumsum -> y coordinates. grid (B*W), block 128 (one thread per h).
// ---------------------------------------------------------------------------
__global__ void __launch_bounds__(128) offset_kernel(
    const float* __restrict__ f, const float* __restrict__ offset_w,
    const float* __restrict__ offset_b, const float* __restrict__ bn_gamma,
    const float* __restrict__ bn_beta, const float* __restrict__ bn_mean,
    const float* __restrict__ bn_var) {
    __shared__ float w_s[64 * 108];        // [c][tap] -> (float4,float4,float) at c*108+tap*12
    __shared__ float rows[3][8][128];      // 8-channel chunk of 3 input rows

    const int bw = blockIdx.x;
    const int b = bw >> 7, w = bw & 127;
    const int h = threadIdx.x;

    // stage weights: offset_w[(k*64 + c)*9 + tap], k = 0..8 only
    for (int i = h; i < 9 * 64 * 9; i += 128) {
        int k = i / 576;
        int r = i - k * 576;
        int c = r / 9, tap = r - (r / 9) * 9;
        w_s[c * 108 + tap * 12 + k] = offset_w[(k * 64 + c) * 9 + tap];
    }

    float acc[9];
    #pragma unroll
    for (int k = 0; k < 9; k++) acc[k] = 0.f;

    for (int cc = 0; cc < 64; cc += 8) {
        __syncthreads();
        for (int i = h; i < 3 * 8 * 128; i += 128) {
            int dy = i / 1024;
            int rem = i - dy * 1024;
            int c = rem >> 7, hh = rem & 127;
            int wr = w + dy - 1;
            float v = 0.f;
            if (wr >= 0 && wr < WW) v = f[((b * CC + cc + c) * WW + wr) * HH + hh];
            rows[dy][c][hh] = v;
        }
        __syncthreads();
        #pragma unroll
        for (int c = 0; c < 8; c++) {
            const float* wb = &w_s[(cc + c) * 108];
            #pragma unroll
            for (int dy = 0; dy < 3; dy++) {
                float vm = (h > 0) ? rows[dy][c][h - 1] : 0.f;
                float vc = rows[dy][c][h];
                float vp = (h < 127) ? rows[dy][c][h + 1] : 0.f;
                #pragma unroll
                for (int dx = 0; dx < 3; dx++) {
                    float v = (dx == 0) ? vm : ((dx == 1) ? vc : vp);
                    const float* wp = wb + (dy * 3 + dx) * 12;
                    float4 w0 = *(const float4*)(wp);
                    float4 w1 = *(const float4*)(wp + 4);
                    float w8 = wp[8];
                    acc[0] = fmaf(v, w0.x, acc[0]);
                    acc[1] = fmaf(v, w0.y, acc[1]);
                    acc[2] = fmaf(v, w0.z, acc[2]);
                    acc[3] = fmaf(v, w0.w, acc[3]);
                    acc[4] = fmaf(v, w1.x, acc[4]);
                    acc[5] = fmaf(v, w1.y, acc[5]);
                    acc[6] = fmaf(v, w1.z, acc[6]);
                    acc[7] = fmaf(v, w1.w, acc[7]);
                    acc[8] = fmaf(v, w8, acc[8]);
                }
            }
        }
    }

    float off[9];
    #pragma unroll
    for (int k = 0; k < 9; k++) {
        float sc = bn_gamma[k] * rsqrtf(bn_var[k] + EPSV);
        off[k] = tanhf((acc[k] + offset_b[k] - bn_mean[k]) * sc + bn_beta[k]);
    }
    // partial cumsum exactly as reference: center=0, edges (0,8) stay raw
    float cum[9];
    cum[4] = 0.f;
    cum[0] = off[0];
    cum[8] = off[8];
    cum[5] = off[5];
    cum[6] = cum[5] + off[6];
    cum[7] = cum[6] + off[7];
    cum[3] = off[3];
    cum[2] = cum[3] + off[2];
    cum[1] = cum[2] + off[1];
    #pragma unroll
    for (int k = 0; k < 9; k++)
        g_y[((b * KK + k) * WW + w) * HH + h] = (float)w + cum[k];
}

// ---------------------------------------------------------------------------
// Kernel Z: zero the GN stats accumulators
// ---------------------------------------------------------------------------
__global__ void zero_stats_kernel() {
    if (threadIdx.x < BB * GG * 2) g_stats[threadIdx.x] = 0.f;
}

// ---------------------------------------------------------------------------
// Kernel B: bilinear gather + (OC x C*K) conv + GN partial sums.
// grid (B*W), block 256. Per k: stage d[h][c] + Wt[c][oc] in smem, then
// register-tiled 4oc x 8h GEMM per thread.
// dks pitch = 66 (NOT a multiple of 4): the GEMM read path then has the two
// half-warp broadcast addresses 528 words apart (bank 0 vs 16) -> conflict-
// free. Consequence: dks stores must be SCALAR (float4 would be misaligned
// for odd h — that was the R1 trap).
// ---------------------------------------------------------------------------
__global__ void __launch_bounds__(256, 2) main_kernel(
    const float* __restrict__ conv_w, const float* __restrict__ conv_b,
    float* __restrict__ out) {
    extern __shared__ float sm[];
    float* Wt = sm;                              // 4096 floats: [c][oc]
    float* dks = sm + 4096;                      // 128*66 floats (pitch 66)
    int* p_idx = (int*)(sm + 4096 + 8448);       // 4*128 base indices
    float* p_wgt = (float*)(p_idx + 512);        // 4*128 bilinear weights

    const int bw = blockIdx.x;
    const int b = bw >> 7, w = bw & 127;
    const int tid = threadIdx.x;
    const int oc4 = tid & 15;                    // oc = oc4*4 (== GN group)
    const int hs = tid >> 4;                     // h base = hs*8
    const int hbase = hs << 3;

    float acc[32];
    #pragma unroll
    for (int i = 0; i < 32; i++) acc[i] = 0.f;

    for (int k = 0; k < KK; k++) {
        __syncthreads();
        // stage weights transposed: Wt[c][oc]
        for (int i = tid; i < 4096; i += 256) {
            int c = i >> 6, oc = i & 63;
            Wt[(c << 6) + oc] = conv_w[((oc << 6) + c) * KK + k];
        }
        // per-h bilinear params
        if (tid < 128) {
            const int h = tid;
            float ys = g_y[((b * KK + k) * WW + w) * HH + h];
            float xs = (float)h + (-5.0f + 1.125f * (float)k);   // linspace(-5,4,9)
            int y0 = (int)floorf(ys);
            y0 = max(0, min(y0, WW - 1));
            int y1 = min(y0 + 1, WW - 1);
            int x0 = (int)floorf(xs);
            x0 = max(0, min(x0, HH - 1));
            int x1 = min(x0 + 1, HH - 1);
            float wy1 = (float)y1 - ys;   // (y1f - ys)
            float wy0 = ys - (float)y0;   // (ys - y0f)
            float wx1 = (float)x1 - xs;
            float wx0 = xs - (float)x0;
            p_idx[0 * 128 + h] = ((b * WW + y0) * HH + x0) << 6;
            p_idx[1 * 128 + h] = ((b * WW + y0) * HH + x1) << 6;
            p_idx[2 * 128 + h] = ((b * WW + y1) * HH + x0) << 6;
            p_idx[3 * 128 + h] = ((b * WW + y1) * HH + x1) << 6;
            p_wgt[0 * 128 + h] = wy1 * wx1;
            p_wgt[1 * 128 + h] = wy1 * wx0;
            p_wgt[2 * 128 + h] = wy0 * wx1;
            p_wgt[3 * 128 + h] = wy0 * wx0;
        }
        __syncthreads();
        // gather: 16 c-quads x 16 h per pass, 8 passes
        #pragma unroll
        for (int pass = 0; pass < 8; pass++) {
            int h = (tid >> 4) + (pass << 4);
            int c = (tid & 15) << 2;
            float4 v0 = *(const float4*)&g_fT[p_idx[h] + c];
            float4 v1 = *(const float4*)&g_fT[p_idx[128 + h] + c];
            float4 v2 = *(const float4*)&g_fT[p_idx[256 + h] + c];
            float4 v3 = *(const float4*)&g_fT[p_idx[384 + h] + c];
            float w0 = p_wgt[h], w1 = p_wgt[128 + h];
            float w2 = p_wgt[256 + h], w3 = p_wgt[384 + h];
            float* dp = &dks[h * 66 + c];
            dp[0] = v0.x * w0 + v1.x * w1 + v2.x * w2 + v3.x * w3;
            dp[1] = v0.y * w0 + v1.y * w1 + v2.y * w2 + v3.y * w3;
            dp[2] = v0.z * w0 + v1.z * w1 + v2.z * w2 + v3.z * w3;
            dp[3] = v0.w * w0 + v1.w * w1 + v2.w * w2 + v3.w * w3;
        }
        __syncthreads();
        // GEMM accumulate: 4 oc x 8 h per thread
        #pragma unroll 8
        for (int c = 0; c < 64; c++) {
            const float4 wv = *(const float4*)&Wt[(c << 6) + (oc4 << 2)];
            #pragma unroll
            for (int j = 0; j < 8; j++) {
                float dv = dks[(hbase + j) * 66 + c];
                acc[j * 4 + 0] = fmaf(dv, wv.x, acc[j * 4 + 0]);
                acc[j * 4 + 1] = fmaf(dv, wv.y, acc[j * 4 + 1]);
                acc[j * 4 + 2] = fmaf(dv, wv.z, acc[j * 4 + 2]);
                acc[j * 4 + 3] = fmaf(dv, wv.w, acc[j * 4 + 3]);
            }
        }
    }

    // epilogue: bias, write z, GN partial sums (thread's oc-quad == one group)
    float s1 = 0.f, s2 = 0.f;
    #pragma unroll
    for (int q = 0; q < 4; q++) {
        const int oc = (oc4 << 2) + q;
        const float bias = conv_b[oc];
        float4 lo, hi;
        lo.x = acc[0 + q] + bias;
        lo.y = acc[4 + q] + bias;
        lo.z = acc[8 + q] + bias;
        lo.w = acc[12 + q] + bias;
        hi.x = acc[16 + q] + bias;
        hi.y = acc[20 + q] + bias;
        hi.z = acc[24 + q] + bias;
        hi.w = acc[28 + q] + bias;
        s1 += lo.x + lo.y + lo.z + lo.w + hi.x + hi.y + hi.z + hi.w;
        s2 += lo.x * lo.x + lo.y * lo.y + lo.z * lo.z + lo.w * lo.w +
              hi.x * hi.x + hi.y * hi.y + hi.z * hi.z + hi.w * hi.w;
        float* op = out + ((b * OCC + oc) * WW + w) * HH + hbase;
        *(float4*)op = lo;
        *(float4*)(op + 4) = hi;
    }
    atomicAdd(&g_stats[(b * GG + oc4) * 2 + 0], s1);
    atomicAdd(&g_stats[(b * GG + oc4) * 2 + 1], s2);
}

// ---------------------------------------------------------------------------
// Kernel C: GroupNorm finalize + ReLU (in place on out)
// ---------------------------------------------------------------------------
__global__ void __launch_bounds__(256) gn_kernel(float* __restrict__ out,
                                                 const float* __restrict__ gn_gamma,
                                                 const float* __restrict__ gn_beta) {
    const int idx = blockIdx.x * 256 + threadIdx.x;   // float4 index
    const int i4 = idx << 2;
    const int oc = (i4 >> 14) & 63;
    const int b = i4 >> 20;
    const int g = oc >> 2;
    const float inv = 1.0f / 65536.0f;
    float s1 = g_stats[(b * GG + g) * 2 + 0];
    float s2 = g_stats[(b * GG + g) * 2 + 1];
    float mean = s1 * inv;
    float var = s2 * inv - mean * mean;
    float sc = gn_gamma[oc] * rsqrtf(var + EPSV);
    float sh = gn_beta[oc] - mean * sc;
    float4* o4 = (float4*)out;
    float4 v = o4[idx];
    v.x = fmaxf(v.x * sc + sh, 0.f);
    v.y = fmaxf(v.y * sc + sh, 0.f);
    v.z = fmaxf(v.z * sc + sh, 0.f);
    v.w = fmaxf(v.w * sc + sh, 0.f);
    o4[idx] = v;
}

// ---------------------------------------------------------------------------
extern "C" void kernel_launch(void* const* d_in, const int* in_sizes, int n_in,
                              void* d_out, int out_size) {
    const float* f        = (const float*)d_in[0];
    const float* offset_w = (const float*)d_in[1];
    const float* offset_b = (const float*)d_in[2];
    const float* bn_gamma = (const float*)d_in[3];
    const float* bn_beta  = (const float*)d_in[4];
    const float* bn_mean  = (const float*)d_in[5];
    const float* bn_var   = (const float*)d_in[6];
    const float* conv_w   = (const float*)d_in[7];
    const float* conv_b   = (const float*)d_in[8];
    const float* gn_gamma = (const float*)d_in[9];
    const float* gn_beta  = (const float*)d_in[10];
    float* out = (float*)d_out;

    const int main_smem = (4096 + 8448) * 4 + 512 * 4 * 2;   // 54272 bytes
    cudaFuncSetAttribute(main_kernel, cudaFuncAttributeMaxDynamicSharedMemorySize,
                         main_smem);

    dim3 tgrid(BB * WW, HH / 32, CC / 32);
    dim3 tblk(32, 8);
    transpose_kernel<<<tgrid, tblk>>>(f);

    offset_kernel<<<BB * WW, 128>>>(f, offset_w, offset_b, bn_gamma, bn_beta,
                                    bn_mean, bn_var);

    zero_stats_kernel<<<1, 128>>>();

    main_kernel<<<BB * WW, 256, main_smem>>>(conv_w, conv_b, out);

    gn_kernel<<<(BB * OCC * WW * HH / 4) / 256, 256>>>(out, gn_gamma, gn_beta);
}